// round 13
// baseline (speedup 1.0000x reference)
#include <cuda_runtime.h>

// Plateau-squeeze version:
//  - loads issued first (hide linMt load + M chain under them)
//  - M computed per-warp by lane 0, broadcast via __shfl_sync: no smem,
//    no __syncthreads, warps proceed independently
//  - grid is exactly full for the benchmark shape -> branchless fast path,
//    predicated slow path only for a possibly-partial last block
#define VEC 4

__device__ __forceinline__ void compute_M(const float* __restrict__ linMt,
                                          const int* __restrict__ Np,
                                          float& m00, float& m01,
                                          float& m10, float& m11) {
    int n = Np[0];
    float b00 = linMt[0], b01 = linMt[1];
    float b10 = linMt[2], b11 = linMt[3];
    float p00 = 1.f, p01 = 0.f, p10 = 0.f, p11 = 1.f;
    while (n > 0) {
        if (n & 1) {
            float t00 = fmaf(p00, b00, p01 * b10);
            float t01 = fmaf(p00, b01, p01 * b11);
            float t10 = fmaf(p10, b00, p11 * b10);
            float t11 = fmaf(p10, b01, p11 * b11);
            p00 = t00; p01 = t01; p10 = t10; p11 = t11;
        }
        n >>= 1;
        if (n > 0) {
            float s00 = fmaf(b00, b00, b01 * b10);
            float s01 = fmaf(b00, b01, b01 * b11);
            float s10 = fmaf(b10, b00, b11 * b10);
            float s11 = fmaf(b10, b01, b11 * b11);
            b00 = s00; b01 = s01; b10 = s10; b11 = s11;
        }
    }
    m00 = p00; m01 = p01; m10 = p10; m11 = p11;
}

__global__ void __launch_bounds__(256) fused_kernel(
    const float4* __restrict__ x, float4* __restrict__ out, int n4,
    const float* __restrict__ linMt, const int* __restrict__ Np,
    const float* __restrict__ xs, float* __restrict__ outs, int n_pairs)
{
    const int base = blockIdx.x * (256 * VEC) + threadIdx.x;
    const bool full = (blockIdx.x + 1) * (256 * VEC) <= n4;

    // 1) Issue streaming loads first — in flight during the M chain.
    float4 v[VEC];
    if (full) {
#pragma unroll
        for (int j = 0; j < VEC; j++) v[j] = __ldg(&x[base + j * 256]);
    } else {
#pragma unroll
        for (int j = 0; j < VEC; j++)
            if (base + j * 256 < n4) v[j] = __ldg(&x[base + j * 256]);
    }

    // 2) Lane 0 of each warp computes M; broadcast via shfl (no barrier).
    float m00, m01, m10, m11;
    if ((threadIdx.x & 31) == 0) {
        compute_M(linMt, Np, m00, m01, m10, m11);
    }
    m00 = __shfl_sync(0xffffffffu, m00, 0);
    m01 = __shfl_sync(0xffffffffu, m01, 0);
    m10 = __shfl_sync(0xffffffffu, m10, 0);
    m11 = __shfl_sync(0xffffffffu, m11, 0);

    // 3) Transform + store.
    if (full) {
#pragma unroll
        for (int j = 0; j < VEC; j++) {
            float4 r;
            r.x = fmaf(v[j].x, m00, v[j].y * m10);
            r.y = fmaf(v[j].x, m01, v[j].y * m11);
            r.z = fmaf(v[j].z, m00, v[j].w * m10);
            r.w = fmaf(v[j].z, m01, v[j].w * m11);
            out[base + j * 256] = r;
        }
    } else {
#pragma unroll
        for (int j = 0; j < VEC; j++) {
            int idx = base + j * 256;
            if (idx < n4) {
                float4 r;
                r.x = fmaf(v[j].x, m00, v[j].y * m10);
                r.y = fmaf(v[j].x, m01, v[j].y * m11);
                r.z = fmaf(v[j].z, m00, v[j].w * m10);
                r.w = fmaf(v[j].z, m01, v[j].w * m11);
                out[idx] = r;
            }
        }
        // Tail pairs (total floats % 4 != 0), handled by one thread.
        if (threadIdx.x == 0) {
            for (int p = n4 * 2; p < n_pairs; p++) {
                float a = xs[2 * p + 0];
                float b = xs[2 * p + 1];
                outs[2 * p + 0] = fmaf(a, m00, b * m10);
                outs[2 * p + 1] = fmaf(a, m01, b * m11);
            }
        }
    }
}

extern "C" void kernel_launch(void* const* d_in, const int* in_sizes, int n_in,
                              void* d_out, int out_size) {
    const float* x     = (const float*)d_in[0];   // (B, 2) float32
    const float* linMt = (const float*)d_in[1];   // (2, 2) float32
    const int*   Np    = (const int*)d_in[2];     // scalar N
    float* out = (float*)d_out;

    int total   = in_sizes[0];   // B * 2 floats
    int n4      = total / 4;     // float4 chunks (2 states each)
    int n_pairs = total / 2;

    int threads = 256;
    int per_block = threads * VEC;
    int blocks = (n4 + per_block - 1) / per_block;
    if (blocks < 1) blocks = 1;

    fused_kernel<<<blocks, threads>>>((const float4*)x, (float4*)out, n4,
                                      linMt, Np, x, out, n_pairs);
}

// round 14
// speedup vs baseline: 1.0486x; 1.0486x over previous
#include <cuda_runtime.h>

// R11 (best: 18.75us kernel) + branchless fast path for full blocks.
// Structure: issue 2x32B streaming loads first; thread 0 computes
// M = linMt^N (fp32 binary exp) into smem under them; barrier; FMA + store.
// Input: ld.global.nc.L2::evict_last (32B). Output: st.global.cs (32B).
#define VEC32 2   // 32-byte chunks per thread

__device__ __forceinline__ void ld32_evict_last(const void* p, float4& a, float4& b) {
    unsigned long long r0, r1, r2, r3;
    asm volatile("ld.global.nc.L2::evict_last.v4.b64 {%0,%1,%2,%3}, [%4];"
                 : "=l"(r0), "=l"(r1), "=l"(r2), "=l"(r3)
                 : "l"(p));
    a.x = __uint_as_float((unsigned)r0); a.y = __uint_as_float((unsigned)(r0 >> 32));
    a.z = __uint_as_float((unsigned)r1); a.w = __uint_as_float((unsigned)(r1 >> 32));
    b.x = __uint_as_float((unsigned)r2); b.y = __uint_as_float((unsigned)(r2 >> 32));
    b.z = __uint_as_float((unsigned)r3); b.w = __uint_as_float((unsigned)(r3 >> 32));
}

__device__ __forceinline__ void st32_cs(void* p, const float4& a, const float4& b) {
    unsigned long long r0 = (unsigned long long)__float_as_uint(a.x)
                          | ((unsigned long long)__float_as_uint(a.y) << 32);
    unsigned long long r1 = (unsigned long long)__float_as_uint(a.z)
                          | ((unsigned long long)__float_as_uint(a.w) << 32);
    unsigned long long r2 = (unsigned long long)__float_as_uint(b.x)
                          | ((unsigned long long)__float_as_uint(b.y) << 32);
    unsigned long long r3 = (unsigned long long)__float_as_uint(b.z)
                          | ((unsigned long long)__float_as_uint(b.w) << 32);
    asm volatile("st.global.cs.v4.b64 [%0], {%1,%2,%3,%4};"
                 :: "l"(p), "l"(r0), "l"(r1), "l"(r2), "l"(r3)
                 : "memory");
}

__device__ __forceinline__ void transform32(const float4& va, const float4& vb,
                                            float m00, float m01, float m10, float m11,
                                            float4& ra, float4& rb) {
    ra.x = fmaf(va.x, m00, va.y * m10);
    ra.y = fmaf(va.x, m01, va.y * m11);
    ra.z = fmaf(va.z, m00, va.w * m10);
    ra.w = fmaf(va.z, m01, va.w * m11);
    rb.x = fmaf(vb.x, m00, vb.y * m10);
    rb.y = fmaf(vb.x, m01, vb.y * m11);
    rb.z = fmaf(vb.z, m00, vb.w * m10);
    rb.w = fmaf(vb.z, m01, vb.w * m11);
}

__global__ void __launch_bounds__(256) fused_kernel(
    const char* __restrict__ xb, char* __restrict__ outb, int n32,
    const float* __restrict__ linMt, const int* __restrict__ Np,
    const float* __restrict__ xs, float* __restrict__ outs, int n_pairs)
{
    __shared__ float sM[4];

    const int base = blockIdx.x * (256 * VEC32) + threadIdx.x;
    const bool full = (blockIdx.x + 1) * (256 * VEC32) <= n32;

    // 1) Issue streaming loads first — in flight while M is computed.
    float4 va[VEC32], vb[VEC32];
    if (full) {
#pragma unroll
        for (int j = 0; j < VEC32; j++)
            ld32_evict_last(xb + (size_t)(base + j * 256) * 32, va[j], vb[j]);
    } else {
#pragma unroll
        for (int j = 0; j < VEC32; j++)
            if (base + j * 256 < n32)
                ld32_evict_last(xb + (size_t)(base + j * 256) * 32, va[j], vb[j]);
    }

    // 2) Thread 0 computes M = linMt^N (fp32 binary exp) into smem.
    if (threadIdx.x == 0) {
        int n = Np[0];
        float b00 = linMt[0], b01 = linMt[1];
        float b10 = linMt[2], b11 = linMt[3];
        float p00 = 1.f, p01 = 0.f, p10 = 0.f, p11 = 1.f;
        while (n > 0) {
            if (n & 1) {
                float t00 = fmaf(p00, b00, p01 * b10);
                float t01 = fmaf(p00, b01, p01 * b11);
                float t10 = fmaf(p10, b00, p11 * b10);
                float t11 = fmaf(p10, b01, p11 * b11);
                p00 = t00; p01 = t01; p10 = t10; p11 = t11;
            }
            n >>= 1;
            if (n > 0) {
                float s00 = fmaf(b00, b00, b01 * b10);
                float s01 = fmaf(b00, b01, b01 * b11);
                float s10 = fmaf(b10, b00, b11 * b10);
                float s11 = fmaf(b10, b01, b11 * b11);
                b00 = s00; b01 = s01; b10 = s10; b11 = s11;
            }
        }
        sM[0] = p00; sM[1] = p01; sM[2] = p10; sM[3] = p11;
    }
    __syncthreads();
    const float m00 = sM[0], m01 = sM[1], m10 = sM[2], m11 = sM[3];

    // 3) Transform + store.
    if (full) {
#pragma unroll
        for (int j = 0; j < VEC32; j++) {
            float4 ra, rb;
            transform32(va[j], vb[j], m00, m01, m10, m11, ra, rb);
            st32_cs(outb + (size_t)(base + j * 256) * 32, ra, rb);
        }
    } else {
#pragma unroll
        for (int j = 0; j < VEC32; j++) {
            int idx = base + j * 256;
            if (idx < n32) {
                float4 ra, rb;
                transform32(va[j], vb[j], m00, m01, m10, m11, ra, rb);
                st32_cs(outb + (size_t)idx * 32, ra, rb);
            }
        }
        // Tail: leftover state pairs if total floats % 8 != 0 (up to 3 pairs).
        if (threadIdx.x == 0) {
            for (int p = n32 * 4; p < n_pairs; p++) {
                float a = xs[2 * p + 0];
                float b = xs[2 * p + 1];
                outs[2 * p + 0] = fmaf(a, m00, b * m10);
                outs[2 * p + 1] = fmaf(a, m01, b * m11);
            }
        }
    }
}

extern "C" void kernel_launch(void* const* d_in, const int* in_sizes, int n_in,
                              void* d_out, int out_size) {
    const float* x     = (const float*)d_in[0];   // (B, 2) float32
    const float* linMt = (const float*)d_in[1];   // (2, 2) float32
    const int*   Np    = (const int*)d_in[2];     // scalar N
    float* out = (float*)d_out;

    int total   = in_sizes[0];   // B * 2 floats
    int n32     = total / 8;     // 32-byte chunks (4 states each)
    int n_pairs = total / 2;

    int threads = 256;
    int per_block = threads * VEC32;
    int blocks = (n32 + per_block - 1) / per_block;
    if (blocks < 1) blocks = 1;

    fused_kernel<<<blocks, threads>>>((const char*)x, (char*)out, n32,
                                      linMt, Np, x, out, n_pairs);
}